// round 6
// baseline (speedup 1.0000x reference)
#include <cuda_runtime.h>
#include <cstdint>

#define NB 8192           // batch
#define A1W 286           // 11*26 conv1 output pixels per batch elem

// ---------------- scratch (device globals; no allocation allowed) ----------
__device__ uint32_t g_lut1[512];                       // conv1+bn1+relu+binarize LUT
__device__ uint32_t g_wpos2[64 * 9];                   // conv2 weight sign bits [oc][tap]
__device__ float    g_c1_2[64], g_c0_2[64];            // conv2 bn affine
__device__ __align__(16) int8_t g_wi8[512 * 3840];     // lin weights as +-1 int8 [n pad512][k']
__device__ uint32_t g_wposO[10 * 16];                  // out weight bits [k][g]
__device__ uint32_t g_A1[NB * A1W];                    // conv1 output, 32ch packed per pixel
__device__ uint32_t g_tT[120 * NB];                    // conv2 output bits, transposed [j][m]
__device__ __align__(16) uint32_t g_B2[NB * 16];       // lin output bits [m][16 words]

__device__ __forceinline__ uint32_t nib2bytes(uint32_t x) {
    // expand 4 bits -> 4 bytes (0/1)
    return (x * 0x00204081u) & 0x01010101u;
}

__device__ __forceinline__ void ldsm_x4(uint32_t& r0, uint32_t& r1, uint32_t& r2, uint32_t& r3,
                                        uint32_t saddr) {
    asm volatile("ldmatrix.sync.aligned.m8n8.x4.shared.b16 {%0,%1,%2,%3}, [%4];"
                 : "=r"(r0), "=r"(r1), "=r"(r2), "=r"(r3) : "r"(saddr));
}

__device__ __forceinline__ void mma_s8(int* c, uint32_t a0, uint32_t a1, uint32_t a2, uint32_t a3,
                                       uint32_t b0, uint32_t b1) {
    asm volatile("mma.sync.aligned.m16n8k32.row.col.s32.s8.s8.s32 "
                 "{%0,%1,%2,%3}, {%4,%5,%6,%7}, {%8,%9}, {%0,%1,%2,%3};"
                 : "+r"(c[0]), "+r"(c[1]), "+r"(c[2]), "+r"(c[3])
                 : "r"(a0), "r"(a1), "r"(a2), "r"(a3), "r"(b0), "r"(b1));
}

// ---------------- prep (misc): LUTs, conv2 weights, out weights ------------
__global__ void prep_misc_kernel(const float* __restrict__ conv1_w, const float* __restrict__ conv1_b,
                                 const float* __restrict__ bn1_g, const float* __restrict__ bn1_b,
                                 const float* __restrict__ bn1_m, const float* __restrict__ bn1_v,
                                 const float* __restrict__ conv2_w, const float* __restrict__ conv2_b,
                                 const float* __restrict__ bn2_g, const float* __restrict__ bn2_b,
                                 const float* __restrict__ bn2_m, const float* __restrict__ bn2_v,
                                 const float* __restrict__ out_w)
{
    int t = threadIdx.x;
    __shared__ uint32_t wb1[32];
    __shared__ float c1s[32], c0s[32];
    if (t < 32) {
        uint32_t wb = 0;
        #pragma unroll
        for (int k = 0; k < 9; k++) wb |= (conv1_w[t * 9 + k] > 0.0f) ? (1u << k) : 0u;
        wb1[t] = wb;
        float inv = __fdiv_rn(bn1_g[t], __fsqrt_rn(bn1_v[t] + 1e-5f));
        c1s[t] = inv;
        c0s[t] = conv1_b[t] * inv + bn1_b[t] - bn1_m[t] * inv;
    }
    __syncthreads();
    for (int idx = t; idx < 512; idx += 256) {
        uint32_t word = 0;
        #pragma unroll
        for (int oc = 0; oc < 32; oc++) {
            int pb = __popc((uint32_t)idx ^ wb1[oc]);
            float s = (float)(9 - 2 * pb);
            float val = fmaf(s, c1s[oc], c0s[oc]);
            if (val > 0.0f) word |= (1u << oc);
        }
        g_lut1[idx] = word;
    }
    for (int e = t; e < 576; e += 256) {
        int oc = e / 9, tap = e % 9;
        uint32_t w = 0;
        #pragma unroll
        for (int c = 0; c < 32; c++)
            w |= (conv2_w[oc * 288 + c * 9 + tap] > 0.0f) ? (1u << c) : 0u;
        g_wpos2[e] = w;
    }
    if (t < 64) {
        float inv = __fdiv_rn(bn2_g[t], __fsqrt_rn(bn2_v[t] + 1e-5f));
        g_c1_2[t] = inv;
        g_c0_2[t] = conv2_b[t] * inv + bn2_b[t] - bn2_m[t] * inv;
    }
    if (t < 160) {
        int k = t / 16, g = t % 16;
        uint32_t w = 0;
        #pragma unroll
        for (int b2 = 0; b2 < 32; b2++) {
            int n = g * 32 + b2;
            if (n < 500 && out_w[k * 500 + n] > 0.0f) w |= (1u << b2);
        }
        g_wposO[t] = w;
    }
}

// ---------------- prep (lin): coalesced read -> +-1 int8, permuted k -------
// k' = j*32 + b : channel c = (j&1)*32 + b, spatial sp = j>>1
__global__ void prep_lin_kernel(const float* __restrict__ lin_w)
{
    __shared__ uint8_t sb[3840];
    int n = blockIdx.x;                 // 0..511
    if (n < 500) {
        const float* row = lin_w + n * 3840;
        for (int i = threadIdx.x; i < 3840; i += 256)
            sb[i] = row[i] > 0.0f ? 1 : 0;
        __syncthreads();
        for (int i = threadIdx.x; i < 3840; i += 256) {
            int c = ((i >> 5) & 1) * 32 + (i & 31);
            int sp = i >> 6;
            g_wi8[n * 3840 + i] = sb[c * 60 + sp] ? (int8_t)1 : (int8_t)-1;
        }
    } else {
        for (int i = threadIdx.x; i < 3840; i += 256)
            g_wi8[n * 3840 + i] = 0;
    }
}

// ---------------- conv1: sign-pack x + 9-bit-patch LUT --------------------
__global__ void conv1_kernel(const float* __restrict__ x)
{
    __shared__ uint32_t rb[24][2];
    __shared__ uint32_t lut[512];
    int t = threadIdx.x;
    int b = blockIdx.x;
    int lane = t & 31, w = t >> 5;
    #pragma unroll
    for (int i = 0; i < 4; i++) lut[t + i * 128] = g_lut1[t + i * 128];
    const float* xb = x + b * 1296;
    for (int r = w; r < 24; r += 4) {
        const float* xr = xb + r * 54;
        uint32_t m0 = __ballot_sync(0xffffffffu, xr[lane] > 0.0f);
        float v2 = (lane < 22) ? xr[32 + lane] : -1.0f;
        uint32_t m1 = __ballot_sync(0xffffffffu, v2 > 0.0f);
        if (lane == 0) { rb[r][0] = m0; rb[r][1] = m1; }
    }
    __syncthreads();
    for (int p = t; p < A1W; p += 128) {
        int oy = p / 26, ox = p % 26;
        int sh = 2 * ox;
        uint32_t idx = 0;
        #pragma unroll
        for (int i = 0; i < 3; i++) {
            int r = 2 * oy + i;
            uint64_t row = (uint64_t)rb[r][0] | ((uint64_t)rb[r][1] << 32);
            idx |= (((uint32_t)(row >> sh)) & 7u) << (3 * i);
        }
        g_A1[b * A1W + p] = lut[idx];
    }
}

// ---------------- conv2: window-batched popcount conv (R5 version) --------
__global__ void __launch_bounds__(128) conv2_kernel()
{
    __shared__ uint32_t sA[4][288];
    __shared__ uint32_t sO[120][4];
    int t = threadIdx.x, warp = t >> 5, lane = t & 31;
    int b0 = blockIdx.x * 4;

    for (int i = t; i < 4 * A1W; i += 128) {
        int e = i / A1W, p = i - e * A1W;
        sA[e][p] = g_A1[(b0 + e) * A1W + p];
    }
    uint32_t w0[9], w1[9];
    #pragma unroll
    for (int k = 0; k < 9; k++) {
        w0[k] = g_wpos2[lane * 9 + k];
        w1[k] = g_wpos2[(lane + 32) * 9 + k];
    }
    float c1a = g_c1_2[lane], c0a = g_c0_2[lane];
    float c1b = g_c1_2[lane + 32], c0b = g_c0_2[lane + 32];
    __syncthreads();

    const uint32_t* A = sA[warp];
    #pragma unroll 1
    for (int oy = 0; oy < 5; oy++) {
        const uint32_t* R = A + oy * 52;
        #pragma unroll
        for (int g = 0; g < 2; g++) {
            uint32_t v[3][13];
            #pragma unroll
            for (int i = 0; i < 3; i++)
                #pragma unroll
                for (int c = 0; c < 13; c++)
                    v[i][c] = R[i * 26 + g * 12 + c];
            int cs[13];
            #pragma unroll
            for (int c = 0; c < 13; c++)
                cs[c] = __popc(v[0][c]) + __popc(v[1][c]) + __popc(v[2][c]);
            #pragma unroll
            for (int px = 0; px < 6; px++) {
                int c0 = px * 2;
                int Asum = cs[c0] + cs[c0 + 1] + cs[c0 + 2];
                int P0 = 0, P1 = 0;
                #pragma unroll
                for (int i = 0; i < 3; i++)
                    #pragma unroll
                    for (int j = 0; j < 3; j++) {
                        uint32_t a = v[i][c0 + j];
                        P0 += __popc(a & w0[i * 3 + j]);
                        P1 += __popc(a & w1[i * 3 + j]);
                    }
                float f0 = fmaf((float)(2 * P0 - Asum), c1a, c0a);
                float f1 = fmaf((float)(2 * P1 - Asum), c1b, c0b);
                uint32_t m0 = __ballot_sync(0xffffffffu, f0 > 0.0f);
                uint32_t m1 = __ballot_sync(0xffffffffu, f1 > 0.0f);
                int sp = oy * 12 + g * 6 + px;
                if (lane == 0) sO[2 * sp][warp] = m0;
                if (lane == 1) sO[2 * sp + 1][warp] = m1;
            }
        }
    }
    __syncthreads();

    for (int i = t; i < 480; i += 128) {
        int j = i >> 2, u = i & 3;
        g_tT[j * NB + b0 + u] = sO[j][u];
    }
}

// ---------------- lin: int8 tensor-core GEMM ------------------------------
// grid = 128 m-tiles(64) x 4 n-groups(128) = 512 blocks; 8 warps = 2m x 4n.
// warp tile: M=32 (2 m16 frags) x N=32 (4 n8 frags) over K=3840 (20 chunks x 192).
#define KW 6                 // k-words per chunk
#define KC (KW * 32)         // 192 k per chunk
#define APITCH 208           // 192 + 16 pad (bytes per A row)
#define BPITCH 208
__global__ void __launch_bounds__(256) lin_kernel(const float* __restrict__ lin_b)
{
    __shared__ __align__(16) uint8_t sA8[64 * APITCH];    // 13.3 KB
    __shared__ __align__(16) uint8_t sB8[128 * BPITCH];   // 26.6 KB
    __shared__ float sbias[128];

    int t = threadIdx.x;
    int w = t >> 5, lane = t & 31;
    int nb = blockIdx.x & 3;            // n-group: 128 n
    int mb = blockIdx.x >> 2;           // m-tile: 64 m
    int warpM = w >> 2, warpN = w & 3;  // 2 x 4
    int mBlock = mb * 64;

    if (t < 128) {
        int gn = nb * 128 + t;
        sbias[t] = (gn < 500) ? lin_b[gn] : 0.0f;
    }

    // per-thread ldmatrix smem addresses (constant row/col pattern)
    uint32_t aBase = (uint32_t)__cvta_generic_to_shared(sA8);
    uint32_t bBase = (uint32_t)__cvta_generic_to_shared(sB8);
    int aRow = warpM * 32 + (lane & 7) + 8 * ((lane >> 3) & 1);
    int aCol = 16 * (lane >> 4);
    uint32_t aAddr0 = aBase + aRow * APITCH + aCol;           // m16 frag 0
    uint32_t aAddr1 = aAddr0 + 16 * APITCH;                   // m16 frag 1
    int bRow = warpN * 32 + (lane & 7) + 8 * (lane >> 4);
    int bCol = 16 * ((lane >> 3) & 1);
    uint32_t bAddr0 = bBase + bRow * BPITCH + bCol;           // n-frags 0,1
    uint32_t bAddr1 = bAddr0 + 16 * BPITCH;                   // n-frags 2,3

    int acc[2][4][4];
    #pragma unroll
    for (int i = 0; i < 2; i++)
        #pragma unroll
        for (int j = 0; j < 4; j++)
            #pragma unroll
            for (int k = 0; k < 4; k++) acc[i][j][k] = 0;

    const int8_t* Bsrc = g_wi8 + (nb * 128) * 3840;

    #pragma unroll 1
    for (int kc = 0; kc < 20; kc++) {
        __syncthreads();
        // stage A bits -> bytes: 6 words x 64 m
        for (int i = t; i < KW * 64; i += 256) {
            int jj = i >> 6, m = i & 63;
            uint32_t W = g_tT[(kc * KW + jj) * NB + mBlock + m];
            uint32_t* dst = (uint32_t*)(sA8 + m * APITCH + jj * 32);
            #pragma unroll
            for (int q = 0; q < 8; q++)
                dst[q] = nib2bytes((W >> (4 * q)) & 0xFu);
        }
        // stage B bytes: 128 n x 192 bytes
        for (int i = t; i < 128 * (KC / 16); i += 256) {
            int n = i / (KC / 16), s = i % (KC / 16);
            *(uint4*)(sB8 + n * BPITCH + s * 16) =
                *(const uint4*)(Bsrc + n * 3840 + kc * KC + s * 16);
        }
        __syncthreads();

        #pragma unroll
        for (int jj = 0; jj < KW; jj++) {
            uint32_t a0[4], a1[4], b0[4], b1[4];
            ldsm_x4(a0[0], a0[1], a0[2], a0[3], aAddr0 + jj * 32);
            ldsm_x4(a1[0], a1[1], a1[2], a1[3], aAddr1 + jj * 32);
            ldsm_x4(b0[0], b0[1], b0[2], b0[3], bAddr0 + jj * 32);
            ldsm_x4(b1[0], b1[1], b1[2], b1[3], bAddr1 + jj * 32);
            mma_s8(acc[0][0], a0[0], a0[1], a0[2], a0[3], b0[0], b0[1]);
            mma_s8(acc[0][1], a0[0], a0[1], a0[2], a0[3], b0[2], b0[3]);
            mma_s8(acc[0][2], a0[0], a0[1], a0[2], a0[3], b1[0], b1[1]);
            mma_s8(acc[0][3], a0[0], a0[1], a0[2], a0[3], b1[2], b1[3]);
            mma_s8(acc[1][0], a1[0], a1[1], a1[2], a1[3], b0[0], b0[1]);
            mma_s8(acc[1][1], a1[0], a1[1], a1[2], a1[3], b0[2], b0[3]);
            mma_s8(acc[1][2], a1[0], a1[1], a1[2], a1[3], b1[0], b1[1]);
            mma_s8(acc[1][3], a1[0], a1[1], a1[2], a1[3], b1[2], b1[3]);
        }
    }

    // epilogue: threshold + assemble 32-bit n-words per m row
    int ng = nb * 4 + warpN;            // output word index 0..15
    int q = lane & 3;
    #pragma unroll
    for (int fm = 0; fm < 2; fm++) {
        uint32_t pl = 0, ph = 0;
        #pragma unroll
        for (int fn = 0; fn < 4; fn++) {
            int nl = fn * 8 + 2 * q;                  // n bit position (and +1)
            int gn = nb * 128 + warpN * 32 + nl;
            float bias0 = sbias[warpN * 32 + nl];
            float bias1 = sbias[warpN * 32 + nl + 1];
            if (gn < 500     && (float)acc[fm][fn][0] + bias0 > 0.0f) pl |= 1u << nl;
            if (gn + 1 < 500 && (float)acc[fm][fn][1] + bias1 > 0.0f) pl |= 1u << (nl + 1);
            if (gn < 500     && (float)acc[fm][fn][2] + bias0 > 0.0f) ph |= 1u << nl;
            if (gn + 1 < 500 && (float)acc[fm][fn][3] + bias1 > 0.0f) ph |= 1u << (nl + 1);
        }
        pl |= __shfl_xor_sync(0xffffffffu, pl, 1);
        pl |= __shfl_xor_sync(0xffffffffu, pl, 2);
        ph |= __shfl_xor_sync(0xffffffffu, ph, 1);
        ph |= __shfl_xor_sync(0xffffffffu, ph, 2);
        if (q == 0) {
            int row = mBlock + warpM * 32 + fm * 16 + (lane >> 2);
            g_B2[row * 16 + ng] = pl;
            g_B2[(row + 8) * 16 + ng] = ph;
        }
    }
}

// ---------------- out: 500->10 popcount matmul -----------------------------
__global__ void out_kernel(const float* __restrict__ out_b, float* __restrict__ y)
{
    __shared__ uint32_t wO[160];
    __shared__ float ob[10];
    int t = threadIdx.x;
    if (t < 160) wO[t] = g_wposO[t];
    if (t < 10)  ob[t] = out_b[t];
    __syncthreads();
    int m = blockIdx.x * 256 + t;
    uint32_t tw[16];
    const uint4* p = reinterpret_cast<const uint4*>(g_B2 + m * 16);
    #pragma unroll
    for (int q = 0; q < 4; q++) {
        uint4 v = p[q];
        tw[q * 4 + 0] = v.x; tw[q * 4 + 1] = v.y;
        tw[q * 4 + 2] = v.z; tw[q * 4 + 3] = v.w;
    }
    int S2 = 0;
    #pragma unroll
    for (int g = 0; g < 16; g++) S2 += __popc(tw[g]);
    #pragma unroll
    for (int k = 0; k < 10; k++) {
        int acc = 0;
        #pragma unroll
        for (int g = 0; g < 16; g++) acc += __popc(tw[g] & wO[k * 16 + g]);
        y[m * 10 + k] = (float)(2 * acc - S2) + ob[k];
    }
}

// ---------------- launch ----------------------------------------------------
extern "C" void kernel_launch(void* const* d_in, const int* in_sizes, int n_in,
                              void* d_out, int out_size)
{
    const float* x       = (const float*)d_in[0];
    const float* conv1_w = (const float*)d_in[1];
    const float* conv1_b = (const float*)d_in[2];
    const float* bn1_g   = (const float*)d_in[3];
    const float* bn1_b   = (const float*)d_in[4];
    const float* bn1_m   = (const float*)d_in[5];
    const float* bn1_v   = (const float*)d_in[6];
    const float* conv2_w = (const float*)d_in[7];
    const float* conv2_b = (const float*)d_in[8];
    const float* bn2_g   = (const float*)d_in[9];
    const float* bn2_b   = (const float*)d_in[10];
    const float* bn2_m   = (const float*)d_in[11];
    const float* bn2_v   = (const float*)d_in[12];
    const float* lin_w   = (const float*)d_in[13];
    const float* lin_b   = (const float*)d_in[14];
    const float* out_w   = (const float*)d_in[15];
    const float* out_b   = (const float*)d_in[16];

    prep_misc_kernel<<<1, 256>>>(conv1_w, conv1_b, bn1_g, bn1_b, bn1_m, bn1_v,
                                 conv2_w, conv2_b, bn2_g, bn2_b, bn2_m, bn2_v,
                                 out_w);
    prep_lin_kernel<<<512, 256>>>(lin_w);
    conv1_kernel<<<NB, 128>>>(x);
    conv2_kernel<<<NB / 4, 128>>>();
    lin_kernel<<<512, 256>>>(lin_b);
    out_kernel<<<NB / 256, 256>>>(out_b, (float*)d_out);
}

// round 7
// speedup vs baseline: 1.6855x; 1.6855x over previous
#include <cuda_runtime.h>
#include <cstdint>

#define NB 8192           // batch
#define A1W 286           // 11*26 conv1 output pixels per batch elem

// ---------------- scratch (device globals; no allocation allowed) ----------
__device__ uint32_t g_lut1[512];                       // conv1+bn1+relu+binarize LUT
__device__ uint32_t g_wpos2[64 * 9];                   // conv2 weight sign bits [oc][tap]
__device__ float    g_c1_2[64], g_c0_2[64];            // conv2 bn affine
__device__ __align__(16) uint32_t g_wposL[512 * 128];  // lin weight bits [n(pad512)][j(pad128)]
__device__ uint32_t g_wposO[10 * 16];                  // out weight bits [k][g]
__device__ uint32_t g_A1[NB * A1W];                    // conv1 output, 32ch packed per pixel
__device__ uint32_t g_tT[120 * NB];                    // conv2 output bits, transposed [j][m]
__device__ __align__(16) uint32_t g_B2[NB * 16];       // lin output bits [m][16 words]

// ---------------- prep (misc): LUTs, conv2 weights, out weights ------------
__global__ void prep_misc_kernel(const float* __restrict__ conv1_w, const float* __restrict__ conv1_b,
                                 const float* __restrict__ bn1_g, const float* __restrict__ bn1_b,
                                 const float* __restrict__ bn1_m, const float* __restrict__ bn1_v,
                                 const float* __restrict__ conv2_w, const float* __restrict__ conv2_b,
                                 const float* __restrict__ bn2_g, const float* __restrict__ bn2_b,
                                 const float* __restrict__ bn2_m, const float* __restrict__ bn2_v,
                                 const float* __restrict__ out_w)
{
    int t = threadIdx.x;
    __shared__ uint32_t wb1[32];
    __shared__ float c1s[32], c0s[32];
    if (t < 32) {
        uint32_t wb = 0;
        #pragma unroll
        for (int k = 0; k < 9; k++) wb |= (conv1_w[t * 9 + k] > 0.0f) ? (1u << k) : 0u;
        wb1[t] = wb;
        float inv = __fdiv_rn(bn1_g[t], __fsqrt_rn(bn1_v[t] + 1e-5f));
        c1s[t] = inv;
        c0s[t] = conv1_b[t] * inv + bn1_b[t] - bn1_m[t] * inv;
    }
    __syncthreads();
    for (int idx = t; idx < 512; idx += 256) {
        uint32_t word = 0;
        #pragma unroll
        for (int oc = 0; oc < 32; oc++) {
            int pb = __popc((uint32_t)idx ^ wb1[oc]);
            float s = (float)(9 - 2 * pb);
            float val = fmaf(s, c1s[oc], c0s[oc]);
            if (val > 0.0f) word |= (1u << oc);
        }
        g_lut1[idx] = word;
    }
    for (int e = t; e < 576; e += 256) {
        int oc = e / 9, tap = e % 9;
        uint32_t w = 0;
        #pragma unroll
        for (int c = 0; c < 32; c++)
            w |= (conv2_w[oc * 288 + c * 9 + tap] > 0.0f) ? (1u << c) : 0u;
        g_wpos2[e] = w;
    }
    if (t < 64) {
        float inv = __fdiv_rn(bn2_g[t], __fsqrt_rn(bn2_v[t] + 1e-5f));
        g_c1_2[t] = inv;
        g_c0_2[t] = conv2_b[t] * inv + bn2_b[t] - bn2_m[t] * inv;
    }
    if (t < 160) {
        int k = t / 16, g = t % 16;
        uint32_t w = 0;
        #pragma unroll
        for (int b2 = 0; b2 < 32; b2++) {
            int n = g * 32 + b2;
            if (n < 500 && out_w[k * 500 + n] > 0.0f) w |= (1u << b2);
        }
        g_wposO[t] = w;
    }
}

// ---------------- prep (lin): coalesced read + smem transpose pack ---------
__global__ void prep_lin_kernel(const float* __restrict__ lin_w)
{
    __shared__ uint8_t sb[3840];
    int n = blockIdx.x;                 // 0..499
    const float* row = lin_w + n * 3840;
    for (int i = threadIdx.x; i < 3840; i += 256)
        sb[i] = row[i] > 0.0f ? 1 : 0;
    __syncthreads();
    for (int j = threadIdx.x; j < 128; j += 256) {
        uint32_t w = 0;
        if (j < 120) {
            int sp = j >> 1;
            int cb = (j & 1) * 32;
            #pragma unroll
            for (int b = 0; b < 32; b++)
                w |= (uint32_t)sb[(cb + b) * 60 + sp] << b;
        }
        g_wposL[n * 128 + j] = w;
    }
}

// ---------------- conv1: sign-pack x + 9-bit-patch LUT --------------------
__global__ void conv1_kernel(const float* __restrict__ x)
{
    __shared__ uint32_t rb[24][2];
    __shared__ uint32_t lut[512];
    int t = threadIdx.x;
    int b = blockIdx.x;
    int lane = t & 31, w = t >> 5;
    #pragma unroll
    for (int i = 0; i < 4; i++) lut[t + i * 128] = g_lut1[t + i * 128];
    const float* xb = x + b * 1296;
    for (int r = w; r < 24; r += 4) {
        const float* xr = xb + r * 54;
        uint32_t m0 = __ballot_sync(0xffffffffu, xr[lane] > 0.0f);
        float v2 = (lane < 22) ? xr[32 + lane] : -1.0f;
        uint32_t m1 = __ballot_sync(0xffffffffu, v2 > 0.0f);
        if (lane == 0) { rb[r][0] = m0; rb[r][1] = m1; }
    }
    __syncthreads();
    for (int p = t; p < A1W; p += 128) {
        int oy = p / 26, ox = p % 26;
        int sh = 2 * ox;
        uint32_t idx = 0;
        #pragma unroll
        for (int i = 0; i < 3; i++) {
            int r = 2 * oy + i;
            uint64_t row = (uint64_t)rb[r][0] | ((uint64_t)rb[r][1] << 32);
            idx |= (((uint32_t)(row >> sh)) & 7u) << (3 * i);
        }
        g_A1[b * A1W + p] = lut[idx];
    }
}

// ---------------- conv2: window-batched popcount conv (R5 version) --------
__global__ void __launch_bounds__(128) conv2_kernel()
{
    __shared__ uint32_t sA[4][288];
    __shared__ uint32_t sO[120][4];
    int t = threadIdx.x, warp = t >> 5, lane = t & 31;
    int b0 = blockIdx.x * 4;

    for (int i = t; i < 4 * A1W; i += 128) {
        int e = i / A1W, p = i - e * A1W;
        sA[e][p] = g_A1[(b0 + e) * A1W + p];
    }
    uint32_t w0[9], w1[9];
    #pragma unroll
    for (int k = 0; k < 9; k++) {
        w0[k] = g_wpos2[lane * 9 + k];
        w1[k] = g_wpos2[(lane + 32) * 9 + k];
    }
    float c1a = g_c1_2[lane], c0a = g_c0_2[lane];
    float c1b = g_c1_2[lane + 32], c0b = g_c0_2[lane + 32];
    __syncthreads();

    const uint32_t* A = sA[warp];
    #pragma unroll 1
    for (int oy = 0; oy < 5; oy++) {
        const uint32_t* R = A + oy * 52;
        #pragma unroll
        for (int g = 0; g < 2; g++) {
            uint32_t v[3][13];
            #pragma unroll
            for (int i = 0; i < 3; i++)
                #pragma unroll
                for (int c = 0; c < 13; c++)
                    v[i][c] = R[i * 26 + g * 12 + c];
            int cs[13];
            #pragma unroll
            for (int c = 0; c < 13; c++)
                cs[c] = __popc(v[0][c]) + __popc(v[1][c]) + __popc(v[2][c]);
            #pragma unroll
            for (int px = 0; px < 6; px++) {
                int c0 = px * 2;
                int Asum = cs[c0] + cs[c0 + 1] + cs[c0 + 2];
                int P0 = 0, P1 = 0;
                #pragma unroll
                for (int i = 0; i < 3; i++)
                    #pragma unroll
                    for (int j = 0; j < 3; j++) {
                        uint32_t a = v[i][c0 + j];
                        P0 += __popc(a & w0[i * 3 + j]);
                        P1 += __popc(a & w1[i * 3 + j]);
                    }
                float f0 = fmaf((float)(2 * P0 - Asum), c1a, c0a);
                float f1 = fmaf((float)(2 * P1 - Asum), c1b, c0b);
                uint32_t m0 = __ballot_sync(0xffffffffu, f0 > 0.0f);
                uint32_t m1 = __ballot_sync(0xffffffffu, f1 > 0.0f);
                int sp = oy * 12 + g * 6 + px;
                if (lane == 0) sO[2 * sp][warp] = m0;
                if (lane == 1) sO[2 * sp + 1][warp] = m1;
            }
        }
    }
    __syncthreads();

    for (int i = t; i < 480; i += 128) {
        int j = i >> 2, u = i & 3;
        g_tT[j * NB + b0 + u] = sO[j][u];
    }
}

// ---------------- lin: popcount GEMM, warp = 32m x 16n (high occupancy) ----
// block = 128 thr = 4 warps covering 128 m x 16 n; grid = 64 m-tiles x 32 ng = 2048.
// Output written as uint16 halves of g_B2 (little-endian positions line up).
__global__ void __launch_bounds__(128) lin_kernel(const float* __restrict__ lin_b)
{
    __shared__ uint4 sw[16][30];        // 16 n rows x 120 words = 7.7 KB
    __shared__ float sbias[16];
    int t = threadIdx.x;
    int ng = blockIdx.x & 31;           // 16-n group
    int mg = (blockIdx.x >> 5) * 4 + (t >> 5);
    int lane = t & 31;

    const uint4* wsrc = reinterpret_cast<const uint4*>(g_wposL) + (ng * 16) * 32;
    for (int i = t; i < 480; i += 128) {
        int n = i / 30, q = i - n * 30;
        sw[n][q] = wsrc[n * 32 + q];
    }
    if (t < 16) {
        int gn = ng * 16 + t;
        sbias[t] = (gn < 500) ? lin_b[gn] : 0.0f;
    }
    __syncthreads();

    int m = mg * 32 + lane;
    int acc[16];
    #pragma unroll
    for (int n = 0; n < 16; n++) acc[n] = 0;
    int S = 0;

    #pragma unroll 1
    for (int kc = 0; kc < 5; kc++) {
        uint32_t tw[24];
        #pragma unroll
        for (int u = 0; u < 24; u++) tw[u] = g_tT[(kc * 24 + u) * NB + m];
        #pragma unroll
        for (int u = 0; u < 24; u++) S += __popc(tw[u]);
        #pragma unroll
        for (int n = 0; n < 16; n++) {
            int p = 0;
            #pragma unroll
            for (int q = 0; q < 6; q++) {
                uint4 wv = sw[n][kc * 6 + q];
                p += __popc(tw[q * 4 + 0] & wv.x);
                p += __popc(tw[q * 4 + 1] & wv.y);
                p += __popc(tw[q * 4 + 2] & wv.z);
                p += __popc(tw[q * 4 + 3] & wv.w);
            }
            acc[n] += p;
        }
    }

    uint32_t bits = 0;
    #pragma unroll
    for (int n = 0; n < 16; n++) {
        int gn = ng * 16 + n;
        if (gn < 500) {
            float pre = (float)(2 * acc[n] - S) + sbias[n];
            if (pre > 0.0f) bits |= (1u << n);
        }
    }
    reinterpret_cast<uint16_t*>(g_B2)[m * 32 + ng] = (uint16_t)bits;
}

// ---------------- out: 500->10 popcount matmul -----------------------------
__global__ void out_kernel(const float* __restrict__ out_b, float* __restrict__ y)
{
    __shared__ uint32_t wO[160];
    __shared__ float ob[10];
    int t = threadIdx.x;
    if (t < 160) wO[t] = g_wposO[t];
    if (t < 10)  ob[t] = out_b[t];
    __syncthreads();
    int m = blockIdx.x * 256 + t;
    uint32_t tw[16];
    const uint4* p = reinterpret_cast<const uint4*>(g_B2 + m * 16);
    #pragma unroll
    for (int q = 0; q < 4; q++) {
        uint4 v = p[q];
        tw[q * 4 + 0] = v.x; tw[q * 4 + 1] = v.y;
        tw[q * 4 + 2] = v.z; tw[q * 4 + 3] = v.w;
    }
    int S2 = 0;
    #pragma unroll
    for (int g = 0; g < 16; g++) S2 += __popc(tw[g]);
    #pragma unroll
    for (int k = 0; k < 10; k++) {
        int acc = 0;
        #pragma unroll
        for (int g = 0; g < 16; g++) acc += __popc(tw[g] & wO[k * 16 + g]);
        y[m * 10 + k] = (float)(2 * acc - S2) + ob[k];
    }
}

// ---------------- launch ----------------------------------------------------
extern "C" void kernel_launch(void* const* d_in, const int* in_sizes, int n_in,
                              void* d_out, int out_size)
{
    const float* x       = (const float*)d_in[0];
    const float* conv1_w = (const float*)d_in[1];
    const float* conv1_b = (const float*)d_in[2];
    const float* bn1_g   = (const float*)d_in[3];
    const float* bn1_b   = (const float*)d_in[4];
    const float* bn1_m   = (const float*)d_in[5];
    const float* bn1_v   = (const float*)d_in[6];
    const float* conv2_w = (const float*)d_in[7];
    const float* conv2_b = (const float*)d_in[8];
    const float* bn2_g   = (const float*)d_in[9];
    const float* bn2_b   = (const float*)d_in[10];
    const float* bn2_m   = (const float*)d_in[11];
    const float* bn2_v   = (const float*)d_in[12];
    const float* lin_w   = (const float*)d_in[13];
    const float* lin_b   = (const float*)d_in[14];
    const float* out_w   = (const float*)d_in[15];
    const float* out_b   = (const float*)d_in[16];

    prep_misc_kernel<<<1, 256>>>(conv1_w, conv1_b, bn1_g, bn1_b, bn1_m, bn1_v,
                                 conv2_w, conv2_b, bn2_g, bn2_b, bn2_m, bn2_v,
                                 out_w);
    prep_lin_kernel<<<500, 256>>>(lin_w);
    conv1_kernel<<<NB, 128>>>(x);
    conv2_kernel<<<NB / 4, 128>>>();
    lin_kernel<<<2048, 128>>>(lin_b);
    out_kernel<<<NB / 256, 256>>>(out_b, (float*)d_out);
}

// round 9
// speedup vs baseline: 2.0610x; 1.2228x over previous
#include <cuda_runtime.h>
#include <cstdint>

#define NB 8192           // batch
#define A1W 286           // 11*26 conv1 output pixels per batch elem

#define MAJ3(a,b,c) (((a)&(b)) | ((c)&((a)|(b))))
#define XOR3(a,b,c) ((a)^(b)^(c))

// ---------------- scratch (device globals; no allocation allowed) ----------
__device__ uint32_t g_lut1[512];                       // conv1+bn1+relu+binarize LUT
__device__ uint32_t g_wpos2[64 * 9];                   // conv2 weight sign bits [oc][tap]
__device__ float    g_c1_2[64], g_c0_2[64];            // conv2 bn affine
__device__ __align__(16) uint32_t g_wposL[512 * 128];  // lin weight bits [n(pad512)][j(pad128)]
__device__ uint32_t g_wposO[10 * 16];                  // out weight bits [k][g]
__device__ uint32_t g_A1[NB * A1W];                    // conv1 output, 32ch packed per pixel
__device__ uint32_t g_tT[120 * NB];                    // conv2 output bits, transposed [j][m]
__device__ __align__(16) uint32_t g_B2[NB * 16];       // lin output bits [m][16 words]

// ---------------- prep (misc): LUTs, conv2 weights, out weights ------------
__global__ void prep_misc_kernel(const float* __restrict__ conv1_w, const float* __restrict__ conv1_b,
                                 const float* __restrict__ bn1_g, const float* __restrict__ bn1_b,
                                 const float* __restrict__ bn1_m, const float* __restrict__ bn1_v,
                                 const float* __restrict__ conv2_w, const float* __restrict__ conv2_b,
                                 const float* __restrict__ bn2_g, const float* __restrict__ bn2_b,
                                 const float* __restrict__ bn2_m, const float* __restrict__ bn2_v,
                                 const float* __restrict__ out_w)
{
    int t = threadIdx.x;
    __shared__ uint32_t wb1[32];
    __shared__ float c1s[32], c0s[32];
    if (t < 32) {
        uint32_t wb = 0;
        #pragma unroll
        for (int k = 0; k < 9; k++) wb |= (conv1_w[t * 9 + k] > 0.0f) ? (1u << k) : 0u;
        wb1[t] = wb;
        float inv = __fdiv_rn(bn1_g[t], __fsqrt_rn(bn1_v[t] + 1e-5f));
        c1s[t] = inv;
        c0s[t] = conv1_b[t] * inv + bn1_b[t] - bn1_m[t] * inv;
    }
    __syncthreads();
    for (int idx = t; idx < 512; idx += 256) {
        uint32_t word = 0;
        #pragma unroll
        for (int oc = 0; oc < 32; oc++) {
            int pb = __popc((uint32_t)idx ^ wb1[oc]);
            float s = (float)(9 - 2 * pb);
            float val = fmaf(s, c1s[oc], c0s[oc]);
            if (val > 0.0f) word |= (1u << oc);
        }
        g_lut1[idx] = word;
    }
    for (int e = t; e < 576; e += 256) {
        int oc = e / 9, tap = e % 9;
        uint32_t w = 0;
        #pragma unroll
        for (int c = 0; c < 32; c++)
            w |= (conv2_w[oc * 288 + c * 9 + tap] > 0.0f) ? (1u << c) : 0u;
        g_wpos2[e] = w;
    }
    if (t < 64) {
        float inv = __fdiv_rn(bn2_g[t], __fsqrt_rn(bn2_v[t] + 1e-5f));
        g_c1_2[t] = inv;
        g_c0_2[t] = conv2_b[t] * inv + bn2_b[t] - bn2_m[t] * inv;
    }
    if (t < 160) {
        int k = t / 16, g = t % 16;
        uint32_t w = 0;
        #pragma unroll
        for (int b2 = 0; b2 < 32; b2++) {
            int n = g * 32 + b2;
            if (n < 500 && out_w[k * 500 + n] > 0.0f) w |= (1u << b2);
        }
        g_wposO[t] = w;
    }
}

// ---------------- prep (lin): coalesced read + smem transpose pack ---------
__global__ void prep_lin_kernel(const float* __restrict__ lin_w)
{
    __shared__ uint8_t sb[3840];
    int n = blockIdx.x;                 // 0..499
    const float* row = lin_w + n * 3840;
    for (int i = threadIdx.x; i < 3840; i += 256)
        sb[i] = row[i] > 0.0f ? 1 : 0;
    __syncthreads();
    for (int j = threadIdx.x; j < 128; j += 256) {
        uint32_t w = 0;
        if (j < 120) {
            int sp = j >> 1;
            int cb = (j & 1) * 32;
            #pragma unroll
            for (int b = 0; b < 32; b++)
                w |= (uint32_t)sb[(cb + b) * 60 + sp] << b;
        }
        g_wposL[n * 128 + j] = w;
    }
}

// ---------------- conv1: sign-pack x + 9-bit-patch LUT --------------------
__global__ void conv1_kernel(const float* __restrict__ x)
{
    __shared__ uint32_t rb[24][2];
    __shared__ uint32_t lut[512];
    int t = threadIdx.x;
    int b = blockIdx.x;
    int lane = t & 31, w = t >> 5;
    #pragma unroll
    for (int i = 0; i < 4; i++) lut[t + i * 128] = g_lut1[t + i * 128];
    const float* xb = x + b * 1296;
    for (int r = w; r < 24; r += 4) {
        const float* xr = xb + r * 54;
        uint32_t m0 = __ballot_sync(0xffffffffu, xr[lane] > 0.0f);
        float v2 = (lane < 22) ? xr[32 + lane] : -1.0f;
        uint32_t m1 = __ballot_sync(0xffffffffu, v2 > 0.0f);
        if (lane == 0) { rb[r][0] = m0; rb[r][1] = m1; }
    }
    __syncthreads();
    for (int p = t; p < A1W; p += 128) {
        int oy = p / 26, ox = p % 26;
        int sh = 2 * ox;
        uint32_t idx = 0;
        #pragma unroll
        for (int i = 0; i < 3; i++) {
            int r = 2 * oy + i;
            uint64_t row = (uint64_t)rb[r][0] | ((uint64_t)rb[r][1] << 32);
            idx |= (((uint32_t)(row >> sh)) & 7u) << (3 * i);
        }
        g_A1[b * A1W + p] = lut[idx];
    }
}

// ---------------- conv2: CSA popcount conv, warp = batch elem --------------
// block = 128 thr = 4 warps = 4 elems; grid = NB/4 = 2048
__global__ void __launch_bounds__(128) conv2_kernel()
{
    __shared__ uint32_t sA[4][288];
    __shared__ uint32_t sO[120][4];
    int t = threadIdx.x, warp = t >> 5, lane = t & 31;
    int b0 = blockIdx.x * 4;

    for (int i = t; i < 4 * A1W; i += 128) {
        int e = i / A1W, p = i - e * A1W;
        sA[e][p] = g_A1[(b0 + e) * A1W + p];
    }
    uint32_t w0[9], w1[9];
    #pragma unroll
    for (int k = 0; k < 9; k++) {
        w0[k] = g_wpos2[lane * 9 + k];
        w1[k] = g_wpos2[(lane + 32) * 9 + k];
    }
    float c1a = g_c1_2[lane], c0a = g_c0_2[lane];
    float c1b = g_c1_2[lane + 32], c0b = g_c0_2[lane + 32];
    __syncthreads();

    const uint32_t* A = sA[warp];
    #pragma unroll 1
    for (int oy = 0; oy < 5; oy++) {
        const uint32_t* R = A + oy * 52;
        #pragma unroll
        for (int g = 0; g < 2; g++) {
            // window: 13 cols x 3 rows
            uint32_t v[3][13];
            #pragma unroll
            for (int i = 0; i < 3; i++)
                #pragma unroll
                for (int c = 0; c < 13; c++)
                    v[i][c] = R[i * 26 + g * 12 + c];
            // column sums via 3:2 CSA: Σpopc(v0..v2) = popc(s) + 2 popc(c)
            int pS[13], pC[13];
            #pragma unroll
            for (int c = 0; c < 13; c++) {
                uint32_t s = XOR3(v[0][c], v[1][c], v[2][c]);
                uint32_t cc = MAJ3(v[0][c], v[1][c], v[2][c]);
                pS[c] = __popc(s);
                pC[c] = __popc(cc);
            }
            #pragma unroll
            for (int px = 0; px < 6; px++) {
                int c0 = px * 2;
                int Asum = (pS[c0] + pS[c0 + 1] + pS[c0 + 2])
                         + 2 * (pC[c0] + pC[c0 + 1] + pC[c0 + 2]);
                // P0/P1 via 9 -> (3s,3c) -> 2-level CSA: 4 POPC each
                int P0, P1;
                {
                    uint32_t t0 = v[0][c0] & w0[0], t1 = v[0][c0+1] & w0[1], t2 = v[0][c0+2] & w0[2];
                    uint32_t t3 = v[1][c0] & w0[3], t4 = v[1][c0+1] & w0[4], t5 = v[1][c0+2] & w0[5];
                    uint32_t t6 = v[2][c0] & w0[6], t7 = v[2][c0+1] & w0[7], t8 = v[2][c0+2] & w0[8];
                    uint32_t s1 = XOR3(t0,t1,t2), cA = MAJ3(t0,t1,t2);
                    uint32_t s2 = XOR3(t3,t4,t5), cB = MAJ3(t3,t4,t5);
                    uint32_t s3 = XOR3(t6,t7,t8), cC = MAJ3(t6,t7,t8);
                    uint32_t Sx = XOR3(s1,s2,s3), C2 = MAJ3(s1,s2,s3);
                    uint32_t S2 = XOR3(cA,cB,cC), C4 = MAJ3(cA,cB,cC);
                    P0 = __popc(Sx) + 2 * (__popc(C2) + __popc(S2)) + 4 * __popc(C4);
                }
                {
                    uint32_t t0 = v[0][c0] & w1[0], t1 = v[0][c0+1] & w1[1], t2 = v[0][c0+2] & w1[2];
                    uint32_t t3 = v[1][c0] & w1[3], t4 = v[1][c0+1] & w1[4], t5 = v[1][c0+2] & w1[5];
                    uint32_t t6 = v[2][c0] & w1[6], t7 = v[2][c0+1] & w1[7], t8 = v[2][c0+2] & w1[8];
                    uint32_t s1 = XOR3(t0,t1,t2), cA = MAJ3(t0,t1,t2);
                    uint32_t s2 = XOR3(t3,t4,t5), cB = MAJ3(t3,t4,t5);
                    uint32_t s3 = XOR3(t6,t7,t8), cC = MAJ3(t6,t7,t8);
                    uint32_t Sx = XOR3(s1,s2,s3), C2 = MAJ3(s1,s2,s3);
                    uint32_t S2 = XOR3(cA,cB,cC), C4 = MAJ3(cA,cB,cC);
                    P1 = __popc(Sx) + 2 * (__popc(C2) + __popc(S2)) + 4 * __popc(C4);
                }
                float f0 = fmaf((float)(2 * P0 - Asum), c1a, c0a);
                float f1 = fmaf((float)(2 * P1 - Asum), c1b, c0b);
                uint32_t m0 = __ballot_sync(0xffffffffu, f0 > 0.0f);
                uint32_t m1 = __ballot_sync(0xffffffffu, f1 > 0.0f);
                int sp = oy * 12 + g * 6 + px;
                if (lane == 0) sO[2 * sp][warp] = m0;
                if (lane == 1) sO[2 * sp + 1][warp] = m1;
            }
        }
    }
    __syncthreads();

    for (int i = t; i < 480; i += 128) {
        int j = i >> 2, u = i & 3;
        g_tT[j * NB + b0 + u] = sO[j][u];
    }
}

// ---------------- lin: CSA popcount GEMM, warp = 32m x 32n -----------------
__global__ void __launch_bounds__(128) lin_kernel(const float* __restrict__ lin_b)
{
    __shared__ uint4 sw[32][30];        // 32 n rows x 120 words = 15 KB
    int t = threadIdx.x;
    int ng = blockIdx.x & 15;
    int mg = (blockIdx.x >> 4) * 4 + (t >> 5);
    int lane = t & 31;

    const uint4* wsrc = reinterpret_cast<const uint4*>(g_wposL) + (ng * 32) * 32;
    for (int i = t; i < 960; i += 128) {
        int n = i / 30, q = i - n * 30;
        sw[n][q] = wsrc[n * 32 + q];
    }
    __syncthreads();

    int m = mg * 32 + lane;
    int acc[32];
    #pragma unroll
    for (int n = 0; n < 32; n++) acc[n] = 0;
    int S = 0;

    #pragma unroll 1
    for (int kc = 0; kc < 5; kc++) {
        uint32_t tw[24];
        #pragma unroll
        for (int u = 0; u < 24; u++) tw[u] = g_tT[(kc * 24 + u) * NB + m];
        // S via CSA on raw activation words
        {
            int ss = 0, sc = 0;
            #pragma unroll
            for (int gtr = 0; gtr < 8; gtr++) {
                uint32_t a0 = tw[3*gtr], a1 = tw[3*gtr+1], a2 = tw[3*gtr+2];
                ss += __popc(XOR3(a0, a1, a2));
                sc += __popc(MAJ3(a0, a1, a2));
            }
            S += ss + 2 * sc;
        }
        #pragma unroll 8
        for (int n = 0; n < 32; n++) {
            uint32_t w[24];
            #pragma unroll
            for (int q = 0; q < 6; q++) {
                uint4 wv = sw[n][kc * 6 + q];
                w[q*4+0] = wv.x; w[q*4+1] = wv.y; w[q*4+2] = wv.z; w[q*4+3] = wv.w;
            }
            int ps = 0, pc = 0;
            #pragma unroll
            for (int gtr = 0; gtr < 8; gtr++) {
                uint32_t t0 = tw[3*gtr]   & w[3*gtr];
                uint32_t t1 = tw[3*gtr+1] & w[3*gtr+1];
                uint32_t t2 = tw[3*gtr+2] & w[3*gtr+2];
                ps += __popc(XOR3(t0, t1, t2));
                pc += __popc(MAJ3(t0, t1, t2));
            }
            acc[n] += ps + 2 * pc;
        }
    }

    uint32_t bits = 0;
    #pragma unroll
    for (int n = 0; n < 32; n++) {
        int gn = ng * 32 + n;
        if (gn < 500) {
            float pre = (float)(2 * acc[n] - S) + lin_b[gn];
            if (pre > 0.0f) bits |= (1u << n);
        }
    }
    g_B2[m * 16 + ng] = bits;
}

// ---------------- out: 500->10 popcount matmul -----------------------------
__global__ void out_kernel(const float* __restrict__ out_b, float* __restrict__ y)
{
    __shared__ uint32_t wO[160];
    __shared__ float ob[10];
    int t = threadIdx.x;
    if (t < 160) wO[t] = g_wposO[t];
    if (t < 10)  ob[t] = out_b[t];
    __syncthreads();
    int m = blockIdx.x * 256 + t;
    uint32_t tw[16];
    const uint4* p = reinterpret_cast<const uint4*>(g_B2 + m * 16);
    #pragma unroll
    for (int q = 0; q < 4; q++) {
        uint4 v = p[q];
        tw[q * 4 + 0] = v.x; tw[q * 4 + 1] = v.y;
        tw[q * 4 + 2] = v.z; tw[q * 4 + 3] = v.w;
    }
    int S2 = 0;
    #pragma unroll
    for (int g = 0; g < 16; g++) S2 += __popc(tw[g]);
    #pragma unroll
    for (int k = 0; k < 10; k++) {
        int acc = 0;
        #pragma unroll
        for (int g = 0; g < 16; g++) acc += __popc(tw[g] & wO[k * 16 + g]);
        y[m * 10 + k] = (float)(2 * acc - S2) + ob[k];
    }
}

// ---------------- launch ----------------------------------------------------
extern "C" void kernel_launch(void* const* d_in, const int* in_sizes, int n_in,
                              void* d_out, int out_size)
{
    const float* x       = (const float*)d_in[0];
    const float* conv1_w = (const float*)d_in[1];
    const float* conv1_b = (const float*)d_in[2];
    const float* bn1_g   = (const float*)d_in[3];
    const float* bn1_b   = (const float*)d_in[4];
    const float* bn1_m   = (const float*)d_in[5];
    const float* bn1_v   = (const float*)d_in[6];
    const float* conv2_w = (const float*)d_in[7];
    const float* conv2_b = (const float*)d_in[8];
    const float* bn2_g   = (const float*)d_in[9];
    const float* bn2_b   = (const float*)d_in[10];
    const float* bn2_m   = (const float*)d_in[11];
    const float* bn2_v   = (const float*)d_in[12];
    const float* lin_w   = (const float*)d_in[13];
    const float* lin_b   = (const float*)d_in[14];
    const float* out_w   = (const float*)d_in[15];
    const float* out_b   = (const float*)d_in[16];

    prep_misc_kernel<<<1, 256>>>(conv1_w, conv1_b, bn1_g, bn1_b, bn1_m, bn1_v,
                                 conv2_w, conv2_b, bn2_g, bn2_b, bn2_m, bn2_v,
                                 out_w);
    prep_lin_kernel<<<500, 256>>>(lin_w);
    conv1_kernel<<<NB, 128>>>(x);
    conv2_kernel<<<NB / 4, 128>>>();
    lin_kernel<<<1024, 128>>>(lin_b);
    out_kernel<<<NB / 256, 256>>>(out_b, (float*)d_out);
}

// round 10
// speedup vs baseline: 2.1475x; 1.0420x over previous
#include <cuda_runtime.h>
#include <cstdint>

#define NB 8192           // batch
#define A1W 286           // 11*26 conv1 output pixels per batch elem

#define MAJ3(a,b,c) (((a)&(b)) | ((c)&((a)|(b))))
#define XOR3(a,b,c) ((a)^(b)^(c))

// ---------------- scratch (device globals; no allocation allowed) ----------
__device__ uint32_t g_lut1[512];                       // conv1+bn1+relu+binarize LUT
__device__ uint32_t g_wpos2[64 * 9];                   // conv2 weight sign bits [oc][tap]
__device__ float    g_c1_2[64], g_c0_2[64];            // conv2 bn affine
__device__ __align__(16) uint32_t g_wposL[512 * 128];  // lin weight bits [n(pad512)][j(pad128)]
__device__ uint32_t g_wposO[10 * 16];                  // out weight bits [k][g]
__device__ uint32_t g_A1[NB * A1W];                    // conv1 output, 32ch packed per pixel
__device__ uint32_t g_tT[120 * NB];                    // conv2 output bits, transposed [j][m]
__device__ __align__(16) uint32_t g_B2[NB * 16];       // lin output bits [m][16 words]

// ---------------- prep (misc): LUTs, conv2 weights, out weights ------------
__global__ void prep_misc_kernel(const float* __restrict__ conv1_w, const float* __restrict__ conv1_b,
                                 const float* __restrict__ bn1_g, const float* __restrict__ bn1_b,
                                 const float* __restrict__ bn1_m, const float* __restrict__ bn1_v,
                                 const float* __restrict__ conv2_w, const float* __restrict__ conv2_b,
                                 const float* __restrict__ bn2_g, const float* __restrict__ bn2_b,
                                 const float* __restrict__ bn2_m, const float* __restrict__ bn2_v,
                                 const float* __restrict__ out_w)
{
    int t = threadIdx.x;
    __shared__ uint32_t wb1[32];
    __shared__ float c1s[32], c0s[32];
    if (t < 32) {
        uint32_t wb = 0;
        #pragma unroll
        for (int k = 0; k < 9; k++) wb |= (conv1_w[t * 9 + k] > 0.0f) ? (1u << k) : 0u;
        wb1[t] = wb;
        float inv = __fdiv_rn(bn1_g[t], __fsqrt_rn(bn1_v[t] + 1e-5f));
        c1s[t] = inv;
        c0s[t] = conv1_b[t] * inv + bn1_b[t] - bn1_m[t] * inv;
    }
    __syncthreads();
    for (int idx = t; idx < 512; idx += 256) {
        uint32_t word = 0;
        #pragma unroll
        for (int oc = 0; oc < 32; oc++) {
            int pb = __popc((uint32_t)idx ^ wb1[oc]);
            float s = (float)(9 - 2 * pb);
            float val = fmaf(s, c1s[oc], c0s[oc]);
            if (val > 0.0f) word |= (1u << oc);
        }
        g_lut1[idx] = word;
    }
    for (int e = t; e < 576; e += 256) {
        int oc = e / 9, tap = e % 9;
        uint32_t w = 0;
        #pragma unroll
        for (int c = 0; c < 32; c++)
            w |= (conv2_w[oc * 288 + c * 9 + tap] > 0.0f) ? (1u << c) : 0u;
        g_wpos2[e] = w;
    }
    if (t < 64) {
        float inv = __fdiv_rn(bn2_g[t], __fsqrt_rn(bn2_v[t] + 1e-5f));
        g_c1_2[t] = inv;
        g_c0_2[t] = conv2_b[t] * inv + bn2_b[t] - bn2_m[t] * inv;
    }
    if (t < 160) {
        int k = t / 16, g = t % 16;
        uint32_t w = 0;
        #pragma unroll
        for (int b2 = 0; b2 < 32; b2++) {
            int n = g * 32 + b2;
            if (n < 500 && out_w[k * 500 + n] > 0.0f) w |= (1u << b2);
        }
        g_wposO[t] = w;
    }
}

// ---------------- prep (lin): coalesced read + smem transpose pack ---------
__global__ void prep_lin_kernel(const float* __restrict__ lin_w)
{
    __shared__ uint8_t sb[3840];
    int n = blockIdx.x;                 // 0..499
    const float* row = lin_w + n * 3840;
    for (int i = threadIdx.x; i < 3840; i += 256)
        sb[i] = row[i] > 0.0f ? 1 : 0;
    __syncthreads();
    for (int j = threadIdx.x; j < 128; j += 256) {
        uint32_t w = 0;
        if (j < 120) {
            int sp = j >> 1;
            int cb = (j & 1) * 32;
            #pragma unroll
            for (int b = 0; b < 32; b++)
                w |= (uint32_t)sb[(cb + b) * 60 + sp] << b;
        }
        g_wposL[n * 128 + j] = w;
    }
}

// ---------------- conv1: sign-pack x + 9-bit-patch LUT --------------------
__global__ void conv1_kernel(const float* __restrict__ x)
{
    __shared__ uint32_t rb[24][2];
    __shared__ uint32_t lut[512];
    int t = threadIdx.x;
    int b = blockIdx.x;
    int lane = t & 31, w = t >> 5;
    #pragma unroll
    for (int i = 0; i < 4; i++) lut[t + i * 128] = g_lut1[t + i * 128];
    const float* xb = x + b * 1296;
    for (int r = w; r < 24; r += 4) {
        const float* xr = xb + r * 54;
        uint32_t m0 = __ballot_sync(0xffffffffu, xr[lane] > 0.0f);
        float v2 = (lane < 22) ? xr[32 + lane] : -1.0f;
        uint32_t m1 = __ballot_sync(0xffffffffu, v2 > 0.0f);
        if (lane == 0) { rb[r][0] = m0; rb[r][1] = m1; }
    }
    __syncthreads();
    for (int p = t; p < A1W; p += 128) {
        int oy = p / 26, ox = p % 26;
        int sh = 2 * ox;
        uint32_t idx = 0;
        #pragma unroll
        for (int i = 0; i < 3; i++) {
            int r = 2 * oy + i;
            uint64_t row = (uint64_t)rb[r][0] | ((uint64_t)rb[r][1] << 32);
            idx |= (((uint32_t)(row >> sh)) & 7u) << (3 * i);
        }
        g_A1[b * A1W + p] = lut[idx];
    }
}

// ---------------- conv2: CSA popcount conv (R9 version, unchanged) ---------
__global__ void __launch_bounds__(128) conv2_kernel()
{
    __shared__ uint32_t sA[4][288];
    __shared__ uint32_t sO[120][4];
    int t = threadIdx.x, warp = t >> 5, lane = t & 31;
    int b0 = blockIdx.x * 4;

    for (int i = t; i < 4 * A1W; i += 128) {
        int e = i / A1W, p = i - e * A1W;
        sA[e][p] = g_A1[(b0 + e) * A1W + p];
    }
    uint32_t w0[9], w1[9];
    #pragma unroll
    for (int k = 0; k < 9; k++) {
        w0[k] = g_wpos2[lane * 9 + k];
        w1[k] = g_wpos2[(lane + 32) * 9 + k];
    }
    float c1a = g_c1_2[lane], c0a = g_c0_2[lane];
    float c1b = g_c1_2[lane + 32], c0b = g_c0_2[lane + 32];
    __syncthreads();

    const uint32_t* A = sA[warp];
    #pragma unroll 1
    for (int oy = 0; oy < 5; oy++) {
        const uint32_t* R = A + oy * 52;
        #pragma unroll
        for (int g = 0; g < 2; g++) {
            uint32_t v[3][13];
            #pragma unroll
            for (int i = 0; i < 3; i++)
                #pragma unroll
                for (int c = 0; c < 13; c++)
                    v[i][c] = R[i * 26 + g * 12 + c];
            int pS[13], pC[13];
            #pragma unroll
            for (int c = 0; c < 13; c++) {
                uint32_t s = XOR3(v[0][c], v[1][c], v[2][c]);
                uint32_t cc = MAJ3(v[0][c], v[1][c], v[2][c]);
                pS[c] = __popc(s);
                pC[c] = __popc(cc);
            }
            #pragma unroll
            for (int px = 0; px < 6; px++) {
                int c0 = px * 2;
                int Asum = (pS[c0] + pS[c0 + 1] + pS[c0 + 2])
                         + 2 * (pC[c0] + pC[c0 + 1] + pC[c0 + 2]);
                int P0, P1;
                {
                    uint32_t t0 = v[0][c0] & w0[0], t1 = v[0][c0+1] & w0[1], t2 = v[0][c0+2] & w0[2];
                    uint32_t t3 = v[1][c0] & w0[3], t4 = v[1][c0+1] & w0[4], t5 = v[1][c0+2] & w0[5];
                    uint32_t t6 = v[2][c0] & w0[6], t7 = v[2][c0+1] & w0[7], t8 = v[2][c0+2] & w0[8];
                    uint32_t s1 = XOR3(t0,t1,t2), cA = MAJ3(t0,t1,t2);
                    uint32_t s2 = XOR3(t3,t4,t5), cB = MAJ3(t3,t4,t5);
                    uint32_t s3 = XOR3(t6,t7,t8), cC = MAJ3(t6,t7,t8);
                    uint32_t Sx = XOR3(s1,s2,s3), C2 = MAJ3(s1,s2,s3);
                    uint32_t S2 = XOR3(cA,cB,cC), C4 = MAJ3(cA,cB,cC);
                    P0 = __popc(Sx) + 2 * (__popc(C2) + __popc(S2)) + 4 * __popc(C4);
                }
                {
                    uint32_t t0 = v[0][c0] & w1[0], t1 = v[0][c0+1] & w1[1], t2 = v[0][c0+2] & w1[2];
                    uint32_t t3 = v[1][c0] & w1[3], t4 = v[1][c0+1] & w1[4], t5 = v[1][c0+2] & w1[5];
                    uint32_t t6 = v[2][c0] & w1[6], t7 = v[2][c0+1] & w1[7], t8 = v[2][c0+2] & w1[8];
                    uint32_t s1 = XOR3(t0,t1,t2), cA = MAJ3(t0,t1,t2);
                    uint32_t s2 = XOR3(t3,t4,t5), cB = MAJ3(t3,t4,t5);
                    uint32_t s3 = XOR3(t6,t7,t8), cC = MAJ3(t6,t7,t8);
                    uint32_t Sx = XOR3(s1,s2,s3), C2 = MAJ3(s1,s2,s3);
                    uint32_t S2 = XOR3(cA,cB,cC), C4 = MAJ3(cA,cB,cC);
                    P1 = __popc(Sx) + 2 * (__popc(C2) + __popc(S2)) + 4 * __popc(C4);
                }
                float f0 = fmaf((float)(2 * P0 - Asum), c1a, c0a);
                float f1 = fmaf((float)(2 * P1 - Asum), c1b, c0b);
                uint32_t m0 = __ballot_sync(0xffffffffu, f0 > 0.0f);
                uint32_t m1 = __ballot_sync(0xffffffffu, f1 > 0.0f);
                int sp = oy * 12 + g * 6 + px;
                if (lane == 0) sO[2 * sp][warp] = m0;
                if (lane == 1) sO[2 * sp + 1][warp] = m1;
            }
        }
    }
    __syncthreads();

    for (int i = t; i < 480; i += 128) {
        int j = i >> 2, u = i & 3;
        g_tT[j * NB + b0 + u] = sO[j][u];
    }
}

// ---------------- lin: 2-level CSA popcount GEMM, warp = 32m x 16n ---------
// block = 128 thr = 4 warps covering 128 m x 16 n; grid = 64 m-tiles x 32 ng = 2048.
__global__ void __launch_bounds__(128) lin_kernel(const float* __restrict__ lin_b)
{
    __shared__ uint4 sw[16][30];        // 16 n rows x 120 words = 7.7 KB
    __shared__ float sbias[16];
    int t = threadIdx.x;
    int ng = blockIdx.x & 31;           // 16-n group
    int mg = (blockIdx.x >> 5) * 4 + (t >> 5);
    int lane = t & 31;

    const uint4* wsrc = reinterpret_cast<const uint4*>(g_wposL) + (ng * 16) * 32;
    for (int i = t; i < 480; i += 128) {
        int n = i / 30, q = i - n * 30;
        sw[n][q] = wsrc[n * 32 + q];
    }
    if (t < 16) {
        int gn = ng * 16 + t;
        sbias[t] = (gn < 500) ? lin_b[gn] : 0.0f;
    }
    __syncthreads();

    int m = mg * 32 + lane;
    int acc[16];
    #pragma unroll
    for (int n = 0; n < 16; n++) acc[n] = 0;
    int S = 0;

    #pragma unroll 1
    for (int kc = 0; kc < 5; kc++) {
        uint32_t tw[24];
        #pragma unroll
        for (int u = 0; u < 24; u++) tw[u] = g_tT[(kc * 24 + u) * NB + m];
        // S via level-1 CSA on raw activation words (amortized over 16 n)
        {
            int ss = 0, sc = 0;
            #pragma unroll
            for (int g = 0; g < 8; g++) {
                uint32_t a0 = tw[3*g], a1 = tw[3*g+1], a2 = tw[3*g+2];
                ss += __popc(XOR3(a0, a1, a2));
                sc += __popc(MAJ3(a0, a1, a2));
            }
            S += ss + 2 * sc;
        }
        #pragma unroll 4
        for (int n = 0; n < 16; n++) {
            uint32_t w[24];
            #pragma unroll
            for (int q = 0; q < 6; q++) {
                uint4 wv = sw[n][kc * 6 + q];
                w[q*4+0] = wv.x; w[q*4+1] = wv.y; w[q*4+2] = wv.z; w[q*4+3] = wv.w;
            }
            uint32_t s[8], c[8];
            #pragma unroll
            for (int g = 0; g < 8; g++) {
                uint32_t t0 = tw[3*g]   & w[3*g];
                uint32_t t1 = tw[3*g+1] & w[3*g+1];
                uint32_t t2 = tw[3*g+2] & w[3*g+2];
                s[g] = XOR3(t0, t1, t2);
                c[g] = MAJ3(t0, t1, t2);
            }
            // level-2: compress 6 of 8 s-words (w1) and 6 of 8 c-words (w2)
            uint32_t a1 = XOR3(s[0], s[1], s[2]), b1 = MAJ3(s[0], s[1], s[2]);
            uint32_t a2 = XOR3(s[3], s[4], s[5]), b2 = MAJ3(s[3], s[4], s[5]);
            uint32_t d1 = XOR3(c[0], c[1], c[2]), e1 = MAJ3(c[0], c[1], c[2]);
            uint32_t d2 = XOR3(c[3], c[4], c[5]), e2 = MAJ3(c[3], c[4], c[5]);
            int p1 = __popc(a1) + __popc(a2) + __popc(s[6]) + __popc(s[7]);
            int p2 = __popc(b1) + __popc(b2) + __popc(d1) + __popc(d2)
                   + __popc(c[6]) + __popc(c[7]);
            int p4 = __popc(e1) + __popc(e2);
            acc[n] += p1 + 2 * p2 + 4 * p4;
        }
    }

    uint32_t bits = 0;
    #pragma unroll
    for (int n = 0; n < 16; n++) {
        int gn = ng * 16 + n;
        if (gn < 500) {
            float pre = (float)(2 * acc[n] - S) + sbias[n];
            if (pre > 0.0f) bits |= (1u << n);
        }
    }
    reinterpret_cast<uint16_t*>(g_B2)[m * 32 + ng] = (uint16_t)bits;
}

// ---------------- out: 500->10 popcount matmul -----------------------------
__global__ void out_kernel(const float* __restrict__ out_b, float* __restrict__ y)
{
    __shared__ uint32_t wO[160];
    __shared__ float ob[10];
    int t = threadIdx.x;
    if (t < 160) wO[t] = g_wposO[t];
    if (t < 10)  ob[t] = out_b[t];
    __syncthreads();
    int m = blockIdx.x * 256 + t;
    uint32_t tw[16];
    const uint4* p = reinterpret_cast<const uint4*>(g_B2 + m * 16);
    #pragma unroll
    for (int q = 0; q < 4; q++) {
        uint4 v = p[q];
        tw[q * 4 + 0] = v.x; tw[q * 4 + 1] = v.y;
        tw[q * 4 + 2] = v.z; tw[q * 4 + 3] = v.w;
    }
    int S2 = 0;
    #pragma unroll
    for (int g = 0; g < 16; g++) S2 += __popc(tw[g]);
    #pragma unroll
    for (int k = 0; k < 10; k++) {
        int acc = 0;
        #pragma unroll
        for (int g = 0; g < 16; g++) acc += __popc(tw[g] & wO[k * 16 + g]);
        y[m * 10 + k] = (float)(2 * acc - S2) + ob[k];
    }
}

// ---------------- launch ----------------------------------------------------
extern "C" void kernel_launch(void* const* d_in, const int* in_sizes, int n_in,
                              void* d_out, int out_size)
{
    const float* x       = (const float*)d_in[0];
    const float* conv1_w = (const float*)d_in[1];
    const float* conv1_b = (const float*)d_in[2];
    const float* bn1_g   = (const float*)d_in[3];
    const float* bn1_b   = (const float*)d_in[4];
    const float* bn1_m   = (const float*)d_in[5];
    const float* bn1_v   = (const float*)d_in[6];
    const float* conv2_w = (const float*)d_in[7];
    const float* conv2_b = (const float*)d_in[8];
    const float* bn2_g   = (const float*)d_in[9];
    const float* bn2_b   = (const float*)d_in[10];
    const float* bn2_m   = (const float*)d_in[11];
    const float* bn2_v   = (const float*)d_in[12];
    const float* lin_w   = (const float*)d_in[13];
    const float* lin_b   = (const float*)d_in[14];
    const float* out_w   = (const float*)d_in[15];
    const float* out_b   = (const float*)d_in[16];

    prep_misc_kernel<<<1, 256>>>(conv1_w, conv1_b, bn1_g, bn1_b, bn1_m, bn1_v,
                                 conv2_w, conv2_b, bn2_g, bn2_b, bn2_m, bn2_v,
                                 out_w);
    prep_lin_kernel<<<500, 256>>>(lin_w);
    conv1_kernel<<<NB, 128>>>(x);
    conv2_kernel<<<NB / 4, 128>>>();
    lin_kernel<<<2048, 128>>>(lin_b);
    out_kernel<<<NB / 256, 256>>>(out_b, (float*)d_out);
}